// round 8
// baseline (speedup 1.0000x reference)
#include <cuda_runtime.h>

// Grouped 3-tap width conv with cyclic rolls, fp32.
// Full-K per block, single kernel node. Grid = 16 k-tiles x 7 heights = 112 blocks.
// Staging with pure-bitfield index math (no per-element divides):
//   input: 1 thread = 1 (o,i) row, 7 LDG -> rolled/dup'd/padded STS.
//   weights: 4 chunks of 128 i, register-double-buffered LDG prefetch -> STS.
// f32x2 mainloop, register accumulation, shfl+smem reduce, plain STG.
//
// y[o,k,n,m] = sum_{i,j} f[o,i,n,m+j] * w[i,k,j],  f[u] = r[u-1] zero-padded,
// r = width-rolled x; height roll baked into the final store index.

#define THREADS  1024
#define NCH      4               // weight chunks
#define CIC      128             // input channels per chunk

// smem layout (bytes)
#define OFF_IN   0                         // packed input [512][2][10] float2 (dup pairs)
#define SZ_IN    (512 * 2 * 10 * 8)        // 81920
#define OFF_WA   (OFF_IN + SZ_IN)          // (w0,w1) pairs [2][CIC*16] ulonglong2
#define SZ_WA    (2 * CIC * 16 * 16)       // 65536
#define OFF_WB   (OFF_WA + SZ_WA)          // w2 pairs [2][CIC*16] ull
#define SZ_WB    (2 * CIC * 16 * 8)        // 32768
#define SMEM_TOT (OFF_WB + SZ_WB)          // 180224

typedef unsigned long long ull;

__device__ __forceinline__ ull ffma2(ull a, ull b, ull c)
{
    ull d;
    asm("fma.rn.f32x2 %0, %1, %2, %3;" : "=l"(d) : "l"(a), "l"(b), "l"(c));
    return d;
}
__device__ __forceinline__ ull fadd2(ull a, ull b)
{
    ull d;
    asm("add.rn.f32x2 %0, %1, %2;" : "=l"(d) : "l"(a), "l"(b));
    return d;
}

__global__ __launch_bounds__(THREADS, 1) void conv_full(const float* __restrict__ x,
                                                        const float* __restrict__ w,
                                                        float* __restrict__ out)
{
    extern __shared__ char dynsmem[];
    float2*     sIn = reinterpret_cast<float2*>(dynsmem + OFF_IN);   // [(i*2+o)*10 + u]
    ulonglong2* sWa = reinterpret_cast<ulonglong2*>(dynsmem + OFF_WA);
    ull*        sWb = reinterpret_cast<ull*>(dynsmem + OFF_WB);

    const int tid = threadIdx.x;
    const int kb  = blockIdx.x;        // 0..15
    const int n   = blockIdx.y;        // 0..6
    const int k0  = kb * 32;

    // ---- weight pair descriptors (bitfield only): p0 = tid, p1 = tid + 1024 ----
    const int il0 = tid >> 4,          kq0 = tid & 15;
    const int il1 = (tid + 1024) >> 4, kq1 = tid & 15;
    const float* wp0 = w + il0 * 1536 + (k0 + kq0) * 3;   // + c*CIC*1536 per chunk
    const float* wp1 = w + il1 * 1536 + (k0 + kq1) * 3;
    float wr[12];                       // regs for one prefetched chunk

#define LOADW(c)  do { \
        const float* g0 = wp0 + (c) * (CIC * 1536); \
        const float* g1 = wp1 + (c) * (CIC * 1536); \
        wr[0] = g0[0];  wr[1] = g0[1];  wr[2] = g0[2]; \
        wr[3] = g0[48]; wr[4] = g0[49]; wr[5] = g0[50]; \
        wr[6] = g1[0];  wr[7] = g1[1];  wr[8] = g1[2]; \
        wr[9] = g1[48]; wr[10] = g1[49]; wr[11] = g1[50]; \
    } while (0)

#define STOREW(b) do { \
        int idx0 = (b) * (CIC * 16) + il0 * 16 + kq0; \
        int idx1 = (b) * (CIC * 16) + il1 * 16 + kq1; \
        float4 a0 = make_float4(wr[0], wr[3], wr[1], wr[4]); \
        *reinterpret_cast<float4*>(&sWa[idx0]) = a0; \
        float2 b0 = make_float2(wr[2], wr[5]); \
        sWb[idx0] = *reinterpret_cast<ull*>(&b0); \
        float4 a1 = make_float4(wr[6], wr[9], wr[7], wr[10]); \
        *reinterpret_cast<float4*>(&sWa[idx1]) = a1; \
        float2 b1 = make_float2(wr[8], wr[11]); \
        sWb[idx1] = *reinterpret_cast<ull*>(&b1); \
    } while (0)

    // ---- input staging: thread = (o,i) row; roll/dup/pad, no divides ----
    {
        int o = tid >> 9, i = tid & 511;
        const float* src = x + (o * 512 + i) * 49 + n * 7;
        float v0 = src[0], v1 = src[1], v2 = src[2], v3 = src[3];
        float v4 = src[4], v5 = src[5], v6 = src[6];
        float2* row = &sIn[(i * 2 + o) * 10];
        // f[u] = t[m=u-1], t[m] = r[(m-1) mod 7]  =>  u=1 <- v6, u=mw+2 <- v(mw) (mw<6)
        row[0] = make_float2(0.f, 0.f);
        row[1] = make_float2(v6, v6);
        row[2] = make_float2(v0, v0);
        row[3] = make_float2(v1, v1);
        row[4] = make_float2(v2, v2);
        row[5] = make_float2(v3, v3);
        row[6] = make_float2(v4, v4);
        row[7] = make_float2(v5, v5);
        row[8] = make_float2(0.f, 0.f);
        row[9] = make_float2(0.f, 0.f);
    }

    // ---- weight pipeline prologue: buf0 <- chunk 0; regs <- chunk 1 ----
    LOADW(0);
    STOREW(0);
    LOADW(1);
    __syncthreads();            // sIn + sW buf0 visible

    // ---- compute roles ----
    const int warp = tid >> 5;         // 0..31
    const int lane = tid & 31;
    const int o    = warp >> 4;        // group
    const int iseg = warp & 15;        // 16 i-segments of 8 per chunk
    const int isub = lane >> 4;
    const int kp   = lane & 15;
    const int i0   = iseg * 8 + isub * 4;   // local i base within chunk (4 per lane)

    ull A[7];
#pragma unroll
    for (int m = 0; m < 7; m++) A[m] = 0ull;

#pragma unroll 1
    for (int c = 0; c < NCH; c++) {
        const int b = c & 1;
        const float2* pin = &sIn[((c * CIC + i0) * 2 + o) * 10];
        const ulonglong2* pwa = &sWa[b * (CIC * 16) + i0 * 16 + kp];
        const ull*        pwb = &sWb[b * (CIC * 16) + i0 * 16 + kp];

#pragma unroll
        for (int tt = 0; tt < 4; tt++) {
            const ulonglong2* pr = reinterpret_cast<const ulonglong2*>(pin + tt * 20);
            ulonglong2 L0 = pr[0];   // p0,p1
            ulonglong2 L1 = pr[1];   // p2,p3
            ulonglong2 L2 = pr[2];   // p4,p5
            ulonglong2 L3 = pr[3];   // p6,p7
            ulonglong2 L4 = pr[4];   // p8,pad
            ulonglong2 W01 = pwa[tt * 16];
            ull        W2  = pwb[tt * 16];
            ull p0 = L0.x, p1 = L0.y, p2 = L1.x, p3 = L1.y;
            ull p4 = L2.x, p5 = L2.y, p6 = L3.x, p7 = L3.y, p8 = L4.x;

            // A[m] += p[m]*w0 + p[m+1]*w1 + p[m+2]*w2
            A[0] = ffma2(p0, W01.x, A[0]); A[0] = ffma2(p1, W01.y, A[0]); A[0] = ffma2(p2, W2, A[0]);
            A[1] = ffma2(p1, W01.x, A[1]); A[1] = ffma2(p2, W01.y, A[1]); A[1] = ffma2(p3, W2, A[1]);
            A[2] = ffma2(p2, W01.x, A[2]); A[2] = ffma2(p3, W01.y, A[2]); A[2] = ffma2(p4, W2, A[2]);
            A[3] = ffma2(p3, W01.x, A[3]); A[3] = ffma2(p4, W01.y, A[3]); A[3] = ffma2(p5, W2, A[3]);
            A[4] = ffma2(p4, W01.x, A[4]); A[4] = ffma2(p5, W01.y, A[4]); A[4] = ffma2(p6, W2, A[4]);
            A[5] = ffma2(p5, W01.x, A[5]); A[5] = ffma2(p6, W01.y, A[5]); A[5] = ffma2(p7, W2, A[5]);
            A[6] = ffma2(p6, W01.x, A[6]); A[6] = ffma2(p7, W01.y, A[6]); A[6] = ffma2(p8, W2, A[6]);
        }

        if (c < NCH - 1) {
            __syncthreads();            // all warps done reading buf (c+1)&1 (from chunk c-1)
            STOREW((c + 1) & 1);        // regs hold chunk c+1
            if (c + 2 < NCH) LOADW(c + 2);
            __syncthreads();            // buf (c+1)&1 visible
        }
    }

    // ---- reduce: merge isub halves (shfl), then 16 isegs via smem ----
#pragma unroll
    for (int m = 0; m < 7; m++) {
        ull other = __shfl_xor_sync(0xffffffffu, A[m], 16);
        A[m] = fadd2(A[m], other);
    }

    float2* red = reinterpret_cast<float2*>(dynsmem);   // 3584 float2 = 28 KB (sIn dead)
    __syncthreads();
    if (isub == 0) {
#pragma unroll
        for (int m = 0; m < 7; m++)
            red[((o * 16 + kp) * 7 + m) * 16 + iseg] = *reinterpret_cast<float2*>(&A[m]);
    }
    __syncthreads();

    if (tid < 224) {                   // (o, kq, m)
        int oo = tid / 112;
        int r  = tid - oo * 112;
        int kq = r / 7;
        int m  = r - kq * 7;
        const float2* src = &red[((oo * 16 + kq) * 7 + m) * 16];
        float sx = 0.f, sy = 0.f;
#pragma unroll
        for (int is = 0; is < 16; is++) { sx += src[is].x; sy += src[is].y; }
        int nOut = n + 1; if (nOut == 7) nOut = 0;       // height roll +1
        int c1 = oo * 512 + k0 + kq;
        out[c1 * 49 + nOut * 7 + m]        = sx;
        out[(c1 + 16) * 49 + nOut * 7 + m] = sy;
    }
}

extern "C" void kernel_launch(void* const* d_in, const int* in_sizes, int n_in,
                              void* d_out, int out_size)
{
    const float* x = (const float*)d_in[0];
    const float* w = (const float*)d_in[1];
    float* out = (float*)d_out;

    cudaFuncSetAttribute(conv_full, cudaFuncAttributeMaxDynamicSharedMemorySize, SMEM_TOT);
    conv_full<<<dim3(16, 7), THREADS, SMEM_TOT>>>(x, w, out);
}

// round 9
// speedup vs baseline: 1.4098x; 1.4098x over previous
#include <cuda_runtime.h>

// Grouped 3-tap width conv with cyclic rolls, fp32. Single kernel node.
// Grid = 16 k-tiles x 7 heights = 112 blocks, 512 threads, full-K in registers.
// Planar input smem (conflict-free staging, pad taps eliminated), raw weight
// smem via double-buffered cp.async (no repack), f32x2 mainloop (19 FFMA2/i),
// shfl+smem reduce, plain stores.
//
// y[o,k,n,m] = sum_j f[m+j]*w_j per (o,i);  f[0]=0, f[1..7]=width-rolled x row,
// f[8]=0; height roll baked into the final store index.

#define THREADS  512
#define NCH      4               // weight chunks
#define CIC      128             // input channels per chunk

#define OFF_IN   0
#define PLANE    16384           // 1024 rows * 16B per plane
#define SZ_IN    (4 * PLANE)     // 65536
#define OFF_W    SZ_IN
#define WBUF     (CIC * 384)     // 49152 B per buffer (128 rows * 96 floats)
#define SMEM_TOT (OFF_W + 2 * WBUF)   // 163840

typedef unsigned long long ull;

__device__ __forceinline__ ull ffma2(ull a, ull b, ull c)
{
    ull d;
    asm("fma.rn.f32x2 %0, %1, %2, %3;" : "=l"(d) : "l"(a), "l"(b), "l"(c));
    return d;
}
__device__ __forceinline__ ull fadd2(ull a, ull b)
{
    ull d;
    asm("add.rn.f32x2 %0, %1, %2;" : "=l"(d) : "l"(a), "l"(b));
    return d;
}
__device__ __forceinline__ ull pack2(float lo, float hi)
{
    float2 t = make_float2(lo, hi);
    return *reinterpret_cast<ull*>(&t);
}
__device__ __forceinline__ void cp16(unsigned saddr, const void* g)
{
    asm volatile("cp.async.cg.shared.global [%0], [%1], 16;" :: "r"(saddr), "l"(g));
}

__global__ __launch_bounds__(THREADS, 1) void conv_full(const float* __restrict__ x,
                                                        const float* __restrict__ w,
                                                        float* __restrict__ out)
{
    extern __shared__ char dynsmem[];
    const unsigned sbase = (unsigned)__cvta_generic_to_shared(dynsmem);
    const int tid = threadIdx.x;
    const int kb  = blockIdx.x;        // 0..15
    const int n   = blockIdx.y;        // 0..6
    const int k0  = kb * 32;

    // ---- weight cp.async descriptors: 3072 float4 per chunk, 6 per thread ----
    int rel[6];
    const float* gp[6];
#pragma unroll
    for (int q = 0; q < 6; q++) {
        int e   = tid + q * THREADS;     // 0..3071
        int il  = e / 24;                // weight row within chunk (0..127)
        int off = e - il * 24;           // float4 within row (0..23)
        rel[q] = il * 384 + off * 16;
        gp[q]  = w + il * 1536 + kb * 96 + off * 4;
    }

#define ISSUEW(c, b) do { \
        unsigned dstb = sbase + OFF_W + (b) * WBUF; \
        const long long adv = (long long)(c) * (CIC * 1536); \
        _Pragma("unroll") \
        for (int q = 0; q < 6; q++) cp16(dstb + rel[q], gp[q] + adv); \
        asm volatile("cp.async.commit_group;"); \
    } while (0)

    ISSUEW(0, 0);
    ISSUEW(1, 1);

    // ---- input staging: thread -> rows rr, rr+512 (row = i*2+o = rr) ----
#pragma unroll
    for (int rr0 = 0; rr0 < 1024; rr0 += THREADS) {
        int rr = rr0 + tid;
        int o  = rr & 1, i = rr >> 1;
        const float* src = x + (o * 512 + i) * 49 + n * 7;
        float v0 = src[0], v1 = src[1], v2 = src[2], v3 = src[3];
        float v4 = src[4], v5 = src[5], v6 = src[6];
        char* base = dynsmem + OFF_IN + rr * 16;          // lane stride 16B: conflict-free
        *reinterpret_cast<float4*>(base)             = make_float4(0.f, 0.f, v6, v6); // f0,f1
        *reinterpret_cast<float4*>(base + PLANE)     = make_float4(v0, v0, v1, v1);   // f2,f3
        *reinterpret_cast<float4*>(base + 2 * PLANE) = make_float4(v2, v2, v3, v3);   // f4,f5
        *reinterpret_cast<float4*>(base + 3 * PLANE) = make_float4(v4, v4, v5, v5);   // f6,f7
    }

    asm volatile("cp.async.wait_group 1;");
    __syncthreads();                   // buf0 + input visible

    // ---- compute roles ----
    const int warp = tid >> 5;         // 0..15
    const int lane = tid & 31;
    const int o    = warp >> 3;        // group 0..1
    const int iseg = warp & 7;         // 0..7
    const int isub = lane >> 4;        // 0..1
    const int kp   = lane & 15;        // channel pair (k0+2kp, k0+2kp+1)
    const int g    = iseg * 2 + isub;  // 0..15: owns 8 i per chunk

    ull A[7];
#pragma unroll
    for (int m = 0; m < 7; m++) A[m] = 0ull;

#pragma unroll 1
    for (int c = 0; c < NCH; c++) {
        const int b = c & 1;
        const char* inBase = dynsmem + OFF_IN + (((c * CIC + g * 8) * 2 + o) << 4);
        const char* wBase  = dynsmem + OFF_W + b * WBUF + g * 8 * 384 + kp * 24;

#pragma unroll
        for (int t = 0; t < 8; t++) {
            const char* ib = inBase + t * 32;            // i+1 -> row+2 -> +32B
            ulonglong2 L0 = *reinterpret_cast<const ulonglong2*>(ib);             // f0,f1
            ulonglong2 L1 = *reinterpret_cast<const ulonglong2*>(ib + PLANE);     // f2,f3
            ulonglong2 L2 = *reinterpret_cast<const ulonglong2*>(ib + 2 * PLANE); // f4,f5
            ulonglong2 L3 = *reinterpret_cast<const ulonglong2*>(ib + 3 * PLANE); // f6,f7
            const float2* wp = reinterpret_cast<const float2*>(wBase + t * 384);
            float2 q0 = wp[0], q1 = wp[1], q2 = wp[2];   // a0,a1 | a2,b0 | b1,b2
            ull W0 = pack2(q0.x, q1.y);                  // (a0,b0)
            ull W1 = pack2(q0.y, q2.x);                  // (a1,b1)
            ull W2 = pack2(q1.x, q2.y);                  // (a2,b2)
            ull p1 = L0.y, p2 = L1.x, p3 = L1.y, p4 = L2.x;
            ull p5 = L2.y, p6 = L3.x, p7 = L3.y;

            // A[m] += f[m]*W0 + f[m+1]*W1 + f[m+2]*W2   (f0 = f8 = 0 dropped)
            A[0] = ffma2(p1, W1, A[0]); A[0] = ffma2(p2, W2, A[0]);
            A[1] = ffma2(p1, W0, A[1]); A[1] = ffma2(p2, W1, A[1]); A[1] = ffma2(p3, W2, A[1]);
            A[2] = ffma2(p2, W0, A[2]); A[2] = ffma2(p3, W1, A[2]); A[2] = ffma2(p4, W2, A[2]);
            A[3] = ffma2(p3, W0, A[3]); A[3] = ffma2(p4, W1, A[3]); A[3] = ffma2(p5, W2, A[3]);
            A[4] = ffma2(p4, W0, A[4]); A[4] = ffma2(p5, W1, A[4]); A[4] = ffma2(p6, W2, A[4]);
            A[5] = ffma2(p5, W0, A[5]); A[5] = ffma2(p6, W1, A[5]); A[5] = ffma2(p7, W2, A[5]);
            A[6] = ffma2(p6, W0, A[6]); A[6] = ffma2(p7, W1, A[6]);
        }

        if (c == 0 || c == 1) {
            __syncthreads();                       // everyone done reading buf b
            ISSUEW(c + 2, b);
            asm volatile("cp.async.wait_group 1;");  // chunk c+1 arrived
            __syncthreads();
        } else if (c == 2) {
            asm volatile("cp.async.wait_group 0;");  // chunk 3 arrived
            __syncthreads();
        }
    }

    // ---- reduce: isub via shfl, isegs via smem (planes region dead) ----
#pragma unroll
    for (int m = 0; m < 7; m++) {
        ull other = __shfl_xor_sync(0xffffffffu, A[m], 16);
        A[m] = fadd2(A[m], other);
    }

    float2* red = reinterpret_cast<float2*>(dynsmem);   // 1792 float2 = 14 KB
    __syncthreads();
    if (isub == 0) {
#pragma unroll
        for (int m = 0; m < 7; m++)
            red[((o * 16 + kp) * 7 + m) * 8 + iseg] = *reinterpret_cast<float2*>(&A[m]);
    }
    __syncthreads();

    if (tid < 224) {                   // (oo, kq, m)
        int oo = tid / 112;
        int r  = tid - oo * 112;
        int kq = r / 7;
        int m  = r - kq * 7;
        const float2* src = &red[((oo * 16 + kq) * 7 + m) * 8];
        float sx = 0.f, sy = 0.f;
#pragma unroll
        for (int is = 0; is < 8; is++) { sx += src[is].x; sy += src[is].y; }
        int nOut = n + 1; if (nOut == 7) nOut = 0;      // height roll +1
        int c1 = oo * 512 + k0 + 2 * kq;                // pair (c1, c1+1)
        out[c1 * 49 + nOut * 7 + m]       = sx;
        out[(c1 + 1) * 49 + nOut * 7 + m] = sy;
    }
}

extern "C" void kernel_launch(void* const* d_in, const int* in_sizes, int n_in,
                              void* d_out, int out_size)
{
    const float* x = (const float*)d_in[0];
    const float* w = (const float*)d_in[1];
    float* out = (float*)d_out;

    cudaFuncSetAttribute(conv_full, cudaFuncAttributeMaxDynamicSharedMemorySize, SMEM_TOT);
    conv_full<<<dim3(16, 7), THREADS, SMEM_TOT>>>(x, w, out);
}